// round 3
// baseline (speedup 1.0000x reference)
#include <cuda_runtime.h>
#include <math.h>
#include <float.h>

#define NN 50000
#define EE 800000
#define E2 (EE + NN)      // edges + self loops = 850000
#define ETEST 100000
#define ETOT 200000

// ---------------- scratch (device globals; 16B-aligned for float4 access) ---
__device__ __align__(16) float g_h1[NN * 64];
__device__ __align__(16) float g_as1[NN * 8];
__device__ __align__(16) float g_ad1[NN * 8];
__device__ __align__(16) float g_m1[NN * 8];
__device__ __align__(16) float g_den1[NN * 8];
__device__ __align__(16) float g_num1[NN * 64];
__device__ __align__(16) float g_z1[NN * 64];

__device__ __align__(16) float g_h2[NN * 64];
__device__ __align__(16) float g_as2[NN];
__device__ __align__(16) float g_ad2[NN];
__device__ __align__(16) float g_m2[NN];
__device__ __align__(16) float g_den2[NN];
__device__ __align__(16) float g_num2[NN * 64];
__device__ __align__(16) float g_z2[NN * 64];

__device__ __align__(16) int g_src[E2];
__device__ __align__(16) int g_dst[E2];

// ---------------- helpers --------------------------------------------------
__device__ __forceinline__ void atomicMaxFloat(float* addr, float val) {
    // ordered-int trick: monotone toward max under both paths, safe concurrently
    if (val >= 0.0f)
        atomicMax((int*)addr, __float_as_int(val));
    else
        atomicMin((unsigned int*)addr, (unsigned int)__float_as_int(val));
}

__device__ __forceinline__ void red_add_v4(float* addr, float4 v) {
    asm volatile("red.global.add.v4.f32 [%0], {%1,%2,%3,%4};"
                 :: "l"(addr), "f"(v.x), "f"(v.y), "f"(v.z), "f"(v.w)
                 : "memory");
}

__device__ __forceinline__ float lrelu(float x) { return x > 0.0f ? x : 0.2f * x; }

__device__ __forceinline__ float dot4(float4 a, float4 b) {
    return fmaf(a.x, b.x, fmaf(a.y, b.y, fmaf(a.z, b.z, a.w * b.w)));
}

// ---------------- edge prep: copy int32 indices, append self loops ----------
__global__ void prep_edges(const int* __restrict__ ei) {
    int e = blockIdx.x * blockDim.x + threadIdx.x;
    if (e >= E2) return;
    if (e < EE) { g_src[e] = ei[e]; g_dst[e] = ei[EE + e]; }
    else        { g_src[e] = e - EE; g_dst[e] = e - EE; }
}

// ---------------- GEMM: [NN,K] @ [K,64] ------------------------------------
template <int K, int LAYER>
__global__ void gemm64(const float* __restrict__ Xin, const float* __restrict__ W) {
    __shared__ float xs[32 * K];
    const float* X = (LAYER == 1) ? Xin : g_z1;
    float* H = (LAYER == 1) ? g_h1 : g_h2;

    int rowBase = blockIdx.x * 32;
    const float4* X4 = reinterpret_cast<const float4*>(X + (size_t)rowBase * K);
    float4* xs4 = reinterpret_cast<float4*>(xs);
    const int nf4 = 32 * K / 4;
    int maxf4 = (NN - rowBase) * (K / 4);  // valid float4s in this block
    for (int i = threadIdx.x; i < nf4; i += 256) {
        float4 v = (i < maxf4) ? X4[i] : make_float4(0.f, 0.f, 0.f, 0.f);
        xs4[i] = v;
    }
    __syncthreads();

    int col = threadIdx.x & 63;
    int r0 = (threadIdx.x >> 6) * 8;
    float acc[8];
#pragma unroll
    for (int r = 0; r < 8; r++) acc[r] = 0.f;

#pragma unroll 4
    for (int k = 0; k < K; k++) {
        float w = __ldg(&W[k * 64 + col]);
#pragma unroll
        for (int r = 0; r < 8; r++) acc[r] = fmaf(xs[(r0 + r) * K + k], w, acc[r]);
    }
#pragma unroll
    for (int r = 0; r < 8; r++) {
        int row = rowBase + r0 + r;
        if (row < NN) H[row * 64 + col] = acc[r];
    }
}

// ---------------- attention scores -----------------------------------------
__global__ void att1_kernel(const float* __restrict__ att_src,
                            const float* __restrict__ att_dst) {
    int t = blockIdx.x * blockDim.x + threadIdx.x;  // t = n*8 + h
    if (t >= NN * 8) return;
    int h = t & 7;
    const float4* hv = reinterpret_cast<const float4*>(g_h1) + (size_t)t * 2;
    float4 v0 = hv[0], v1 = hv[1];
    const float4* s4 = reinterpret_cast<const float4*>(att_src) + h * 2;
    const float4* d4 = reinterpret_cast<const float4*>(att_dst) + h * 2;
    g_as1[t] = dot4(v0, s4[0]) + dot4(v1, s4[1]);
    g_ad1[t] = dot4(v0, d4[0]) + dot4(v1, d4[1]);
}

__global__ void att2_kernel(const float* __restrict__ att_src,
                            const float* __restrict__ att_dst) {
    int n = blockIdx.x * blockDim.x + threadIdx.x;
    if (n >= NN) return;
    const float4* hv = reinterpret_cast<const float4*>(g_h2) + (size_t)n * 16;
    const float4* s4 = reinterpret_cast<const float4*>(att_src);
    const float4* d4 = reinterpret_cast<const float4*>(att_dst);
    float a_s = 0.f, a_d = 0.f;
#pragma unroll
    for (int i = 0; i < 16; i++) {
        float4 v = hv[i];
        a_s += dot4(v, s4[i]);
        a_d += dot4(v, d4[i]);
    }
    g_as2[n] = a_s;
    g_ad2[n] = a_d;
}

// ---------------- per-launch init ------------------------------------------
__global__ void init1_kernel() {
    int t = blockIdx.x * blockDim.x + threadIdx.x;
    if (t < NN * 64) g_num1[t] = 0.f;
    if (t < NN * 8) { g_den1[t] = 0.f; g_m1[t] = -FLT_MAX; }
}
__global__ void init2_kernel() {
    int t = blockIdx.x * blockDim.x + threadIdx.x;
    if (t < NN * 64) g_num2[t] = 0.f;
    if (t < NN) { g_den2[t] = 0.f; g_m2[t] = -FLT_MAX; }
}

// ---------------- edge passes, layer 1 (H=8, C=8) --------------------------
__global__ void max1_kernel() {
    int t = blockIdx.x * blockDim.x + threadIdx.x;
    if (t >= E2 * 8) return;
    int e = t >> 3, h = t & 7;
    int s = g_src[e], d = g_dst[e];
    float alpha = lrelu(g_as1[s * 8 + h] + g_ad1[d * 8 + h]);
    atomicMaxFloat(&g_m1[d * 8 + h], alpha);
}

__global__ void accum1_kernel() {
    int t = blockIdx.x * blockDim.x + threadIdx.x;
    if (t >= E2 * 8) return;
    int e = t >> 3, h = t & 7;
    int s = g_src[e], d = g_dst[e];
    float alpha = lrelu(g_as1[s * 8 + h] + g_ad1[d * 8 + h]);
    float ex = __expf(alpha - g_m1[d * 8 + h]);
    atomicAdd(&g_den1[d * 8 + h], ex);
    const float4* hv = reinterpret_cast<const float4*>(g_h1) + (size_t)s * 16 + h * 2;
    float4 a = hv[0], b = hv[1];
    a.x *= ex; a.y *= ex; a.z *= ex; a.w *= ex;
    b.x *= ex; b.y *= ex; b.z *= ex; b.w *= ex;
    float* base = &g_num1[d * 64 + h * 8];
    red_add_v4(base, a);
    red_add_v4(base + 4, b);
}

__global__ void fin1_kernel(const float* __restrict__ bias) {
    int t = blockIdx.x * blockDim.x + threadIdx.x;
    if (t >= NN * 64) return;
    int n = t >> 6, c = t & 63, h = c >> 3;
    float v = g_num1[t] / fmaxf(g_den1[n * 8 + h], 1e-16f) + bias[c];
    g_z1[t] = v > 0.f ? v : expm1f(v);  // ELU(alpha=1)
}

// ---------------- edge passes, layer 2 (H=1, C=64) -------------------------
__global__ void max2_kernel() {
    int e = blockIdx.x * blockDim.x + threadIdx.x;
    if (e >= E2) return;
    int s = g_src[e], d = g_dst[e];
    float alpha = lrelu(g_as2[s] + g_ad2[d]);
    atomicMaxFloat(&g_m2[d], alpha);
}

__global__ void accum2_kernel() {
    int t = blockIdx.x * blockDim.x + threadIdx.x;
    if (t >= E2 * 4) return;
    int e = t >> 2, q = t & 3;
    int s = g_src[e], d = g_dst[e];
    float alpha = lrelu(g_as2[s] + g_ad2[d]);
    float ex = __expf(alpha - g_m2[d]);
    if (q == 0) atomicAdd(&g_den2[d], ex);
    const float4* hv = reinterpret_cast<const float4*>(g_h2) + (size_t)s * 16 + q * 4;
    float* base = &g_num2[d * 64 + q * 16];
#pragma unroll
    for (int i = 0; i < 4; i++) {
        float4 v = hv[i];
        v.x *= ex; v.y *= ex; v.z *= ex; v.w *= ex;
        red_add_v4(base + i * 4, v);
    }
}

__global__ void fin2_kernel(const float* __restrict__ bias) {
    int t = blockIdx.x * blockDim.x + threadIdx.x;
    if (t >= NN * 64) return;
    int n = t >> 6, c = t & 63;
    g_z2[t] = g_num2[t] / fmaxf(g_den2[n], 1e-16f) + bias[c];
}

// ---------------- link prediction logits -----------------------------------
__global__ void logits_kernel(const int* __restrict__ pos,
                              const int* __restrict__ neg,
                              float* __restrict__ out) {
    int t = blockIdx.x * blockDim.x + threadIdx.x;
    if (t >= ETOT) return;
    int s, d;
    if (t < ETEST) { s = pos[t]; d = pos[ETEST + t]; }
    else           { s = neg[t - ETEST]; d = neg[ETEST + (t - ETEST)]; }
    const float4* a = reinterpret_cast<const float4*>(g_z2) + (size_t)s * 16;
    const float4* b = reinterpret_cast<const float4*>(g_z2) + (size_t)d * 16;
    float acc = 0.f;
#pragma unroll
    for (int i = 0; i < 16; i++) acc += dot4(a[i], b[i]);
    out[t] = acc;
}

// ---------------- launch ----------------------------------------------------
extern "C" void kernel_launch(void* const* d_in, const int* in_sizes, int n_in,
                              void* d_out, int out_size) {
    const float* x    = (const float*)d_in[0];
    const int*   ei   = (const int*)d_in[1];
    const int*   pos  = (const int*)d_in[2];
    const int*   neg  = (const int*)d_in[3];
    const float* W1   = (const float*)d_in[4];
    const float* as1  = (const float*)d_in[5];
    const float* ad1  = (const float*)d_in[6];
    const float* b1   = (const float*)d_in[7];
    const float* W2   = (const float*)d_in[8];
    const float* as2  = (const float*)d_in[9];
    const float* ad2  = (const float*)d_in[10];
    const float* b2   = (const float*)d_in[11];
    float* out = (float*)d_out;

    const int TB = 256;
    prep_edges<<<(E2 + TB - 1) / TB, TB>>>(ei);
    // layer 1
    gemm64<128, 1><<<(NN + 31) / 32, TB>>>(x, W1);
    att1_kernel<<<(NN * 8 + TB - 1) / TB, TB>>>(as1, ad1);
    init1_kernel<<<(NN * 64 + TB - 1) / TB, TB>>>();
    max1_kernel<<<(E2 * 8 + TB - 1) / TB, TB>>>();
    accum1_kernel<<<(E2 * 8 + TB - 1) / TB, TB>>>();
    fin1_kernel<<<(NN * 64 + TB - 1) / TB, TB>>>(b1);
    // layer 2
    gemm64<64, 2><<<(NN + 31) / 32, TB>>>(nullptr, W2);
    att2_kernel<<<(NN + TB - 1) / TB, TB>>>(as2, ad2);
    init2_kernel<<<(NN * 64 + TB - 1) / TB, TB>>>();
    max2_kernel<<<(E2 + TB - 1) / TB, TB>>>();
    accum2_kernel<<<(E2 * 4 + TB - 1) / TB, TB>>>();
    fin2_kernel<<<(NN * 64 + TB - 1) / TB, TB>>>(b2);
    // logits
    logits_kernel<<<(ETOT + TB - 1) / TB, TB>>>(pos, neg, out);
}

// round 4
// speedup vs baseline: 1.1598x; 1.1598x over previous
#include <cuda_runtime.h>
#include <math.h>
#include <float.h>

#define NN 50000
#define EE 800000
#define E2 (EE + NN)      // edges + self loops = 850000
#define ETEST 100000
#define ETOT 200000

// ---------------- scratch (device globals) ----------------------------------
__device__ __align__(16) float g_h1[NN * 64];
__device__ __align__(16) float g_as1[NN * 8];
__device__ __align__(16) float g_ad1[NN * 8];
__device__ __align__(16) float g_z1[NN * 64];

__device__ __align__(16) float g_h2[NN * 64];
__device__ __align__(16) float g_as2[NN];
__device__ __align__(16) float g_ad2[NN];
__device__ __align__(16) float g_z2[NN * 64];

__device__ __align__(16) int g_deg[NN];
__device__ __align__(16) int g_off[NN + 1];
__device__ __align__(16) int g_cur[NN];
__device__ __align__(16) int g_csr_src[E2];

// ---------------- helpers --------------------------------------------------
__device__ __forceinline__ float lrelu(float x) { return x > 0.0f ? x : 0.2f * x; }

__device__ __forceinline__ float dot4(float4 a, float4 b) {
    return fmaf(a.x, b.x, fmaf(a.y, b.y, fmaf(a.z, b.z, a.w * b.w)));
}

// ---------------- CSR build -------------------------------------------------
__global__ void zero_deg() {
    int t = blockIdx.x * blockDim.x + threadIdx.x;
    if (t < NN) g_deg[t] = 0;
}

__global__ void count_deg(const int* __restrict__ ei) {
    int e = blockIdx.x * blockDim.x + threadIdx.x;
    if (e >= E2) return;
    int d = (e < EE) ? ei[EE + e] : (e - EE);
    atomicAdd(&g_deg[d], 1);
}

__global__ void scan_kernel() {
    __shared__ int ssum[1024];
    const int CH = (NN + 1023) / 1024;  // 49
    int t = threadIdx.x;
    int base = t * CH;
    int s = 0;
    for (int i = 0; i < CH; i++) {
        int idx = base + i;
        if (idx < NN) s += g_deg[idx];
    }
    ssum[t] = s;
    __syncthreads();
    for (int off = 1; off < 1024; off <<= 1) {
        int v = (t >= off) ? ssum[t - off] : 0;
        __syncthreads();
        ssum[t] += v;
        __syncthreads();
    }
    int run = (t == 0) ? 0 : ssum[t - 1];
    for (int i = 0; i < CH; i++) {
        int idx = base + i;
        if (idx < NN) {
            g_off[idx] = run;
            g_cur[idx] = run;
            run += g_deg[idx];
        }
    }
    if (t == 1023) g_off[NN] = E2;
}

__global__ void scatter_kernel(const int* __restrict__ ei) {
    int e = blockIdx.x * blockDim.x + threadIdx.x;
    if (e >= E2) return;
    int s, d;
    if (e < EE) { s = ei[e]; d = ei[EE + e]; }
    else        { s = e - EE; d = s; }
    int pos = atomicAdd(&g_cur[d], 1);
    g_csr_src[pos] = s;
}

// ---------------- GEMM: [NN,K] @ [K,64] ------------------------------------
template <int K, int LAYER>
__global__ void gemm64(const float* __restrict__ Xin, const float* __restrict__ W) {
    __shared__ float xs[32 * K];
    const float* X = (LAYER == 1) ? Xin : g_z1;
    float* H = (LAYER == 1) ? g_h1 : g_h2;

    int rowBase = blockIdx.x * 32;
    const float4* X4 = reinterpret_cast<const float4*>(X + (size_t)rowBase * K);
    float4* xs4 = reinterpret_cast<float4*>(xs);
    const int nf4 = 32 * K / 4;
    int maxf4 = (NN - rowBase) * (K / 4);
    for (int i = threadIdx.x; i < nf4; i += 256) {
        float4 v = (i < maxf4) ? X4[i] : make_float4(0.f, 0.f, 0.f, 0.f);
        xs4[i] = v;
    }
    __syncthreads();

    int col = threadIdx.x & 63;
    int r0 = (threadIdx.x >> 6) * 8;
    float acc[8];
#pragma unroll
    for (int r = 0; r < 8; r++) acc[r] = 0.f;

#pragma unroll 4
    for (int k = 0; k < K; k++) {
        float w = __ldg(&W[k * 64 + col]);
#pragma unroll
        for (int r = 0; r < 8; r++) acc[r] = fmaf(xs[(r0 + r) * K + k], w, acc[r]);
    }
#pragma unroll
    for (int r = 0; r < 8; r++) {
        int row = rowBase + r0 + r;
        if (row < NN) H[row * 64 + col] = acc[r];
    }
}

// ---------------- attention scores -----------------------------------------
__global__ void att1_kernel(const float* __restrict__ att_src,
                            const float* __restrict__ att_dst) {
    int t = blockIdx.x * blockDim.x + threadIdx.x;  // t = n*8 + h
    if (t >= NN * 8) return;
    int h = t & 7;
    const float4* hv = reinterpret_cast<const float4*>(g_h1) + (size_t)t * 2;
    float4 v0 = hv[0], v1 = hv[1];
    const float4* s4 = reinterpret_cast<const float4*>(att_src) + h * 2;
    const float4* d4 = reinterpret_cast<const float4*>(att_dst) + h * 2;
    g_as1[t] = dot4(v0, s4[0]) + dot4(v1, s4[1]);
    g_ad1[t] = dot4(v0, d4[0]) + dot4(v1, d4[1]);
}

__global__ void att2_kernel(const float* __restrict__ att_src,
                            const float* __restrict__ att_dst) {
    int n = blockIdx.x * blockDim.x + threadIdx.x;
    if (n >= NN) return;
    const float4* hv = reinterpret_cast<const float4*>(g_h2) + (size_t)n * 16;
    const float4* s4 = reinterpret_cast<const float4*>(att_src);
    const float4* d4 = reinterpret_cast<const float4*>(att_dst);
    float a_s = 0.f, a_d = 0.f;
#pragma unroll
    for (int i = 0; i < 16; i++) {
        float4 v = hv[i];
        a_s += dot4(v, s4[i]);
        a_d += dot4(v, d4[i]);
    }
    g_as2[n] = a_s;
    g_ad2[n] = a_d;
}

// ---------------- layer-1 aggregation: warp per dst (H=8, C=8) --------------
__global__ void agg1_kernel(const float* __restrict__ bias) {
    int warp = (blockIdx.x * blockDim.x + threadIdx.x) >> 5;
    int lane = threadIdx.x & 31;
    if (warp >= NN) return;
    int d = warp;
    int beg = g_off[d], end = g_off[d + 1];

    float adh = (lane < 8) ? g_ad1[d * 8 + lane] : 0.f;
    int h0 = lane >> 3;          // head of channel 'lane'      (0..3)
    int h1i = 4 + (lane >> 3);   // head of channel 'lane + 32' (4..7)

    float num0 = 0.f, num1 = 0.f, den0 = 0.f, den1 = 0.f;
    int s = (beg < end) ? g_csr_src[beg] : 0;
    for (int i = beg; i < end; i++) {
        int snext = (i + 1 < end) ? g_csr_src[i + 1] : 0;
        float a = 0.f;
        if (lane < 8) a = __expf(lrelu(g_as1[s * 8 + lane] + adh));
        float e0 = __shfl_sync(0xffffffffu, a, h0);
        float e1 = __shfl_sync(0xffffffffu, a, h1i);
        float v0 = g_h1[s * 64 + lane];
        float v1 = g_h1[s * 64 + 32 + lane];
        num0 = fmaf(e0, v0, num0); den0 += e0;
        num1 = fmaf(e1, v1, num1); den1 += e1;
        s = snext;
    }
    float o0 = num0 / fmaxf(den0, 1e-16f) + bias[lane];
    float o1 = num1 / fmaxf(den1, 1e-16f) + bias[32 + lane];
    g_z1[d * 64 + lane]      = o0 > 0.f ? o0 : expm1f(o0);  // ELU
    g_z1[d * 64 + 32 + lane] = o1 > 0.f ? o1 : expm1f(o1);
}

// ---------------- layer-2 aggregation: warp per dst (H=1, C=64) -------------
__global__ void agg2_kernel(const float* __restrict__ bias) {
    int warp = (blockIdx.x * blockDim.x + threadIdx.x) >> 5;
    int lane = threadIdx.x & 31;
    if (warp >= NN) return;
    int d = warp;
    int beg = g_off[d], end = g_off[d + 1];

    float ad = g_ad2[d];
    float num0 = 0.f, num1 = 0.f, den = 0.f;
    int s = (beg < end) ? g_csr_src[beg] : 0;
    for (int i = beg; i < end; i++) {
        int snext = (i + 1 < end) ? g_csr_src[i + 1] : 0;
        float ex = __expf(lrelu(g_as2[s] + ad));
        num0 = fmaf(ex, g_h2[s * 64 + lane], num0);
        num1 = fmaf(ex, g_h2[s * 64 + 32 + lane], num1);
        den += ex;
        s = snext;
    }
    float inv = 1.0f / fmaxf(den, 1e-16f);
    g_z2[d * 64 + lane]      = num0 * inv + bias[lane];
    g_z2[d * 64 + 32 + lane] = num1 * inv + bias[32 + lane];
}

// ---------------- link prediction logits -----------------------------------
__global__ void logits_kernel(const int* __restrict__ pos,
                              const int* __restrict__ neg,
                              float* __restrict__ out) {
    int t = blockIdx.x * blockDim.x + threadIdx.x;
    if (t >= ETOT) return;
    int s, d;
    if (t < ETEST) { s = pos[t]; d = pos[ETEST + t]; }
    else           { s = neg[t - ETEST]; d = neg[ETEST + (t - ETEST)]; }
    const float4* a = reinterpret_cast<const float4*>(g_z2) + (size_t)s * 16;
    const float4* b = reinterpret_cast<const float4*>(g_z2) + (size_t)d * 16;
    float acc = 0.f;
#pragma unroll
    for (int i = 0; i < 16; i++) acc += dot4(a[i], b[i]);
    out[t] = acc;
}

// ---------------- launch ----------------------------------------------------
extern "C" void kernel_launch(void* const* d_in, const int* in_sizes, int n_in,
                              void* d_out, int out_size) {
    const float* x    = (const float*)d_in[0];
    const int*   ei   = (const int*)d_in[1];
    const int*   pos  = (const int*)d_in[2];
    const int*   neg  = (const int*)d_in[3];
    const float* W1   = (const float*)d_in[4];
    const float* as1  = (const float*)d_in[5];
    const float* ad1  = (const float*)d_in[6];
    const float* b1   = (const float*)d_in[7];
    const float* W2   = (const float*)d_in[8];
    const float* as2  = (const float*)d_in[9];
    const float* ad2  = (const float*)d_in[10];
    const float* b2   = (const float*)d_in[11];
    float* out = (float*)d_out;

    const int TB = 256;
    // CSR build
    zero_deg<<<(NN + TB - 1) / TB, TB>>>();
    count_deg<<<(E2 + TB - 1) / TB, TB>>>(ei);
    scan_kernel<<<1, 1024>>>();
    scatter_kernel<<<(E2 + TB - 1) / TB, TB>>>(ei);
    // layer 1
    gemm64<128, 1><<<(NN + 31) / 32, TB>>>(x, W1);
    att1_kernel<<<(NN * 8 + TB - 1) / TB, TB>>>(as1, ad1);
    agg1_kernel<<<(NN * 32 + TB - 1) / TB, TB>>>(b1);
    // layer 2
    gemm64<64, 2><<<(NN + 31) / 32, TB>>>(nullptr, W2);
    att2_kernel<<<(NN + TB - 1) / TB, TB>>>(as2, ad2);
    agg2_kernel<<<(NN * 32 + TB - 1) / TB, TB>>>(b2);
    // logits
    logits_kernel<<<(ETOT + TB - 1) / TB, TB>>>(pos, neg, out);
}

// round 5
// speedup vs baseline: 1.2137x; 1.0465x over previous
#include <cuda_runtime.h>
#include <math.h>
#include <float.h>

#define NN 50000
#define EE 800000
#define E2 (EE + NN)      // edges + self loops = 850000
#define ETEST 100000
#define ETOT 200000

// ---------------- scratch (device globals) ----------------------------------
__device__ __align__(16) float g_h1[NN * 64];
__device__ __align__(16) float g_as1[NN * 8];
__device__ __align__(16) float g_ad1[NN * 8];
__device__ __align__(16) float g_z1[NN * 64];

__device__ __align__(16) float g_h2[NN * 64];
__device__ __align__(16) float g_as2[NN];
__device__ __align__(16) float g_ad2[NN];
__device__ __align__(16) float g_z2[NN * 64];

__device__ __align__(16) int g_deg[NN];
__device__ __align__(16) int g_off[NN + 1];
__device__ __align__(16) int g_cur[NN];
__device__ __align__(16) int g_csr_src[E2];

// ---------------- helpers --------------------------------------------------
__device__ __forceinline__ float lrelu(float x) { return x > 0.0f ? x : 0.2f * x; }

__device__ __forceinline__ float dot4(float4 a, float4 b) {
    return fmaf(a.x, b.x, fmaf(a.y, b.y, fmaf(a.z, b.z, a.w * b.w)));
}

// ---------------- CSR build -------------------------------------------------
__global__ void zero_deg() {
    int t = blockIdx.x * blockDim.x + threadIdx.x;
    if (t < NN) g_deg[t] = 0;
}

__global__ void count_deg(const int* __restrict__ ei) {
    int e0 = (blockIdx.x * blockDim.x + threadIdx.x) * 4;
#pragma unroll
    for (int j = 0; j < 4; j++) {
        int e = e0 + j;
        if (e < E2) {
            int d = (e < EE) ? ei[EE + e] : (e - EE);
            atomicAdd(&g_deg[d], 1);
        }
    }
}

__global__ void scan_kernel() {
    __shared__ int ssum[1024];
    const int CH = (NN + 1023) / 1024;  // 49
    int t = threadIdx.x;
    int base = t * CH;
    int s = 0;
    for (int i = 0; i < CH; i++) {
        int idx = base + i;
        if (idx < NN) s += g_deg[idx];
    }
    ssum[t] = s;
    __syncthreads();
    for (int off = 1; off < 1024; off <<= 1) {
        int v = (t >= off) ? ssum[t - off] : 0;
        __syncthreads();
        ssum[t] += v;
        __syncthreads();
    }
    int run = (t == 0) ? 0 : ssum[t - 1];
    for (int i = 0; i < CH; i++) {
        int idx = base + i;
        if (idx < NN) {
            g_off[idx] = run;
            g_cur[idx] = run;
            run += g_deg[idx];
        }
    }
    if (t == 1023) g_off[NN] = E2;
}

__global__ void scatter_kernel(const int* __restrict__ ei) {
    int e0 = (blockIdx.x * blockDim.x + threadIdx.x) * 4;
#pragma unroll
    for (int j = 0; j < 4; j++) {
        int e = e0 + j;
        if (e < E2) {
            int s, d;
            if (e < EE) { s = ei[e]; d = ei[EE + e]; }
            else        { s = e - EE; d = s; }
            int pos = atomicAdd(&g_cur[d], 1);
            g_csr_src[pos] = s;
        }
    }
}

// ---------------- fused GEMM + attention scores ------------------------------
// [NN,K] @ [K,64]; block tile 64 rows x 64 cols, 256 threads, thread tile 4x4.
// Lane layout: cg = tid&15 (4 cols), rg = tid>>4 (4 rows). A warp holds 16 cg
// x 2 rg -> 16 lanes share each xs read (smem broadcast).
// Epilogue computes a_src/a_dst from acc registers (no separate att kernel).
template <int K, int LAYER>
__global__ void gemm_att(const float* __restrict__ Xin, const float* __restrict__ W,
                         const float* __restrict__ att_s, const float* __restrict__ att_d) {
    __shared__ float xs[64 * 64];
    __shared__ float ws[64 * 64];
    const float* X = (LAYER == 1) ? Xin : g_z1;
    float* H = (LAYER == 1) ? g_h1 : g_h2;

    int tid = threadIdx.x;
    int cg = tid & 15;        // col group (4 cols)
    int rg = tid >> 4;        // row group (4 rows)
    int rowBase = blockIdx.x * 64;

    float acc[4][4];
#pragma unroll
    for (int a = 0; a < 4; a++)
#pragma unroll
        for (int b = 0; b < 4; b++) acc[a][b] = 0.f;

    const float4* X4 = reinterpret_cast<const float4*>(X);
    const float4* W4 = reinterpret_cast<const float4*>(W);

    for (int kc = 0; kc < K; kc += 64) {
        // load x chunk: 64 rows x 64 k (1024 float4)
#pragma unroll
        for (int i = tid; i < 1024; i += 256) {
            int row = i >> 4, q = i & 15;
            float4 v = (rowBase + row < NN)
                ? X4[(size_t)(rowBase + row) * (K / 4) + (kc / 4) + q]
                : make_float4(0.f, 0.f, 0.f, 0.f);
            *reinterpret_cast<float4*>(&xs[row * 64 + q * 4]) = v;
        }
        // load W chunk: rows kc..kc+63 of [K,64] (1024 float4)
#pragma unroll
        for (int i = tid; i < 1024; i += 256) {
            *reinterpret_cast<float4*>(&ws[i * 4]) = W4[kc * 16 + i];
        }
        __syncthreads();

#pragma unroll 4
        for (int k = 0; k < 64; k++) {
            float4 wv = *reinterpret_cast<const float4*>(&ws[k * 64 + cg * 4]);
            float x0 = xs[(rg * 4 + 0) * 64 + k];
            float x1 = xs[(rg * 4 + 1) * 64 + k];
            float x2 = xs[(rg * 4 + 2) * 64 + k];
            float x3 = xs[(rg * 4 + 3) * 64 + k];
            acc[0][0] = fmaf(x0, wv.x, acc[0][0]); acc[0][1] = fmaf(x0, wv.y, acc[0][1]);
            acc[0][2] = fmaf(x0, wv.z, acc[0][2]); acc[0][3] = fmaf(x0, wv.w, acc[0][3]);
            acc[1][0] = fmaf(x1, wv.x, acc[1][0]); acc[1][1] = fmaf(x1, wv.y, acc[1][1]);
            acc[1][2] = fmaf(x1, wv.z, acc[1][2]); acc[1][3] = fmaf(x1, wv.w, acc[1][3]);
            acc[2][0] = fmaf(x2, wv.x, acc[2][0]); acc[2][1] = fmaf(x2, wv.y, acc[2][1]);
            acc[2][2] = fmaf(x2, wv.z, acc[2][2]); acc[2][3] = fmaf(x2, wv.w, acc[2][3]);
            acc[3][0] = fmaf(x3, wv.x, acc[3][0]); acc[3][1] = fmaf(x3, wv.y, acc[3][1]);
            acc[3][2] = fmaf(x3, wv.z, acc[3][2]); acc[3][3] = fmaf(x3, wv.w, acc[3][3]);
        }
        __syncthreads();
    }

    // att weights for this thread's 4 columns
    float aw_s[4], aw_d[4];
#pragma unroll
    for (int cc = 0; cc < 4; cc++) {
        aw_s[cc] = __ldg(&att_s[cg * 4 + cc]);
        aw_d[cc] = __ldg(&att_d[cg * 4 + cc]);
    }

#pragma unroll
    for (int rr = 0; rr < 4; rr++) {
        int row = rowBase + rg * 4 + rr;
        bool ok = row < NN;
        // store H
        if (ok) {
            float4 hv = make_float4(acc[rr][0], acc[rr][1], acc[rr][2], acc[rr][3]);
            *reinterpret_cast<float4*>(&H[(size_t)row * 64 + cg * 4]) = hv;
        }
        // attention partials over this thread's 4 cols
        float ps = 0.f, pd = 0.f;
#pragma unroll
        for (int cc = 0; cc < 4; cc++) {
            ps = fmaf(acc[rr][cc], aw_s[cc], ps);
            pd = fmaf(acc[rr][cc], aw_d[cc], pd);
        }
        if (LAYER == 1) {
            // head = cg>>1; combine cg pairs (8 cols per head)
            ps += __shfl_xor_sync(0xffffffffu, ps, 1);
            pd += __shfl_xor_sync(0xffffffffu, pd, 1);
            if (!(cg & 1) && ok) {
                g_as1[row * 8 + (cg >> 1)] = ps;
                g_ad1[row * 8 + (cg >> 1)] = pd;
            }
        } else {
            // full 64-col reduction across 16 cg lanes
            ps += __shfl_xor_sync(0xffffffffu, ps, 1);
            pd += __shfl_xor_sync(0xffffffffu, pd, 1);
            ps += __shfl_xor_sync(0xffffffffu, ps, 2);
            pd += __shfl_xor_sync(0xffffffffu, pd, 2);
            ps += __shfl_xor_sync(0xffffffffu, ps, 4);
            pd += __shfl_xor_sync(0xffffffffu, pd, 4);
            ps += __shfl_xor_sync(0xffffffffu, ps, 8);
            pd += __shfl_xor_sync(0xffffffffu, pd, 8);
            if (cg == 0 && ok) {
                g_as2[row] = ps;
                g_ad2[row] = pd;
            }
        }
    }
}

// ---------------- layer-1 aggregation: warp per dst (H=8, C=8) --------------
__global__ void agg1_kernel(const float* __restrict__ bias) {
    int warp = (blockIdx.x * blockDim.x + threadIdx.x) >> 5;
    int lane = threadIdx.x & 31;
    if (warp >= NN) return;
    int d = warp;
    int beg = g_off[d], end = g_off[d + 1];

    float adh = (lane < 8) ? g_ad1[d * 8 + lane] : 0.f;
    int h0 = lane >> 3;          // head of channel 'lane'
    int h1i = 4 + (lane >> 3);   // head of channel 'lane + 32'

    float num0 = 0.f, num1 = 0.f, den0 = 0.f, den1 = 0.f;
    // depth-1 software pipeline
    int s = (beg < end) ? g_csr_src[beg] : 0;
    float aS = (lane < 8) ? g_as1[s * 8 + lane] : 0.f;
    float v0 = g_h1[s * 64 + lane];
    float v1 = g_h1[s * 64 + 32 + lane];
    for (int i = beg; i < end; i++) {
        int snext = 0; float aSn = 0.f, v0n = 0.f, v1n = 0.f;
        if (i + 1 < end) {
            snext = g_csr_src[i + 1];
            if (lane < 8) aSn = g_as1[snext * 8 + lane];
            v0n = g_h1[snext * 64 + lane];
            v1n = g_h1[snext * 64 + 32 + lane];
        }
        float a = (lane < 8) ? __expf(lrelu(aS + adh)) : 0.f;
        float e0 = __shfl_sync(0xffffffffu, a, h0);
        float e1 = __shfl_sync(0xffffffffu, a, h1i);
        num0 = fmaf(e0, v0, num0); den0 += e0;
        num1 = fmaf(e1, v1, num1); den1 += e1;
        s = snext; aS = aSn; v0 = v0n; v1 = v1n;
    }
    float o0 = num0 / fmaxf(den0, 1e-16f) + bias[lane];
    float o1 = num1 / fmaxf(den1, 1e-16f) + bias[32 + lane];
    g_z1[d * 64 + lane]      = o0 > 0.f ? o0 : expm1f(o0);  // ELU
    g_z1[d * 64 + 32 + lane] = o1 > 0.f ? o1 : expm1f(o1);
}

// ---------------- layer-2 aggregation: warp per dst (H=1, C=64) -------------
__global__ void agg2_kernel(const float* __restrict__ bias) {
    int warp = (blockIdx.x * blockDim.x + threadIdx.x) >> 5;
    int lane = threadIdx.x & 31;
    if (warp >= NN) return;
    int d = warp;
    int beg = g_off[d], end = g_off[d + 1];

    float ad = g_ad2[d];
    float num0 = 0.f, num1 = 0.f, den = 0.f;
    int s = (beg < end) ? g_csr_src[beg] : 0;
    float aS = g_as2[s];
    float v0 = g_h2[s * 64 + lane];
    float v1 = g_h2[s * 64 + 32 + lane];
    for (int i = beg; i < end; i++) {
        int snext = 0; float aSn = 0.f, v0n = 0.f, v1n = 0.f;
        if (i + 1 < end) {
            snext = g_csr_src[i + 1];
            aSn = g_as2[snext];
            v0n = g_h2[snext * 64 + lane];
            v1n = g_h2[snext * 64 + 32 + lane];
        }
        float ex = __expf(lrelu(aS + ad));
        num0 = fmaf(ex, v0, num0);
        num1 = fmaf(ex, v1, num1);
        den += ex;
        s = snext; aS = aSn; v0 = v0n; v1 = v1n;
    }
    float inv = 1.0f / fmaxf(den, 1e-16f);
    g_z2[d * 64 + lane]      = num0 * inv + bias[lane];
    g_z2[d * 64 + 32 + lane] = num1 * inv + bias[32 + lane];
}

// ---------------- link prediction logits -----------------------------------
__global__ void logits_kernel(const int* __restrict__ pos,
                              const int* __restrict__ neg,
                              float* __restrict__ out) {
    int t = blockIdx.x * blockDim.x + threadIdx.x;
    if (t >= ETOT) return;
    int s, d;
    if (t < ETEST) { s = pos[t]; d = pos[ETEST + t]; }
    else           { s = neg[t - ETEST]; d = neg[ETEST + (t - ETEST)]; }
    const float4* a = reinterpret_cast<const float4*>(g_z2) + (size_t)s * 16;
    const float4* b = reinterpret_cast<const float4*>(g_z2) + (size_t)d * 16;
    float acc = 0.f;
#pragma unroll
    for (int i = 0; i < 16; i++) acc += dot4(a[i], b[i]);
    out[t] = acc;
}

// ---------------- launch ----------------------------------------------------
extern "C" void kernel_launch(void* const* d_in, const int* in_sizes, int n_in,
                              void* d_out, int out_size) {
    const float* x    = (const float*)d_in[0];
    const int*   ei   = (const int*)d_in[1];
    const int*   pos  = (const int*)d_in[2];
    const int*   neg  = (const int*)d_in[3];
    const float* W1   = (const float*)d_in[4];
    const float* as1  = (const float*)d_in[5];
    const float* ad1  = (const float*)d_in[6];
    const float* b1   = (const float*)d_in[7];
    const float* W2   = (const float*)d_in[8];
    const float* as2  = (const float*)d_in[9];
    const float* ad2  = (const float*)d_in[10];
    const float* b2   = (const float*)d_in[11];
    float* out = (float*)d_out;

    const int TB = 256;
    const int E4 = (E2 + 3) / 4;
    // CSR build
    zero_deg<<<(NN + TB - 1) / TB, TB>>>();
    count_deg<<<(E4 + TB - 1) / TB, TB>>>(ei);
    scan_kernel<<<1, 1024>>>();
    scatter_kernel<<<(E4 + TB - 1) / TB, TB>>>(ei);
    // layer 1 (GEMM + att fused)
    gemm_att<128, 1><<<(NN + 63) / 64, TB>>>(x, W1, as1, ad1);
    agg1_kernel<<<(NN * 32 + TB - 1) / TB, TB>>>(b1);
    // layer 2
    gemm_att<64, 2><<<(NN + 63) / 64, TB>>>(nullptr, W2, as2, ad2);
    agg2_kernel<<<(NN * 32 + TB - 1) / TB, TB>>>(b2);
    // logits
    logits_kernel<<<(ETOT + TB - 1) / TB, TB>>>(pos, neg, out);
}